// round 11
// baseline (speedup 1.0000x reference)
#include <cuda_runtime.h>
#include <cstdint>
#include <cstddef>

#define NG   50
#define NF   64
#define DIM  128

typedef unsigned long long ull;

// ---------------- f32x2 helpers (Blackwell packed fp32) ----------------
__device__ __forceinline__ ull pk2(float lo, float hi){
    ull r; asm("mov.b64 %0, {%1, %2};" : "=l"(r) : "f"(lo), "f"(hi)); return r;
}
__device__ __forceinline__ float2 up2(ull v){
    float2 f; asm("mov.b64 {%0, %1}, %2;" : "=f"(f.x), "=f"(f.y) : "l"(v)); return f;
}
__device__ __forceinline__ ull ffma2(ull a, ull b, ull c){
    ull d; asm("fma.rn.f32x2 %0, %1, %2, %3;" : "=l"(d) : "l"(a), "l"(b), "l"(c)); return d;
}
__device__ __forceinline__ ull fadd2(ull a, ull b){
    ull d; asm("add.rn.f32x2 %0, %1, %2;" : "=l"(d) : "l"(a), "l"(b)); return d;
}

// shifted softplus
__device__ __forceinline__ float sspf(float x){
    float e = __expf(-fabsf(x));
    return fmaxf(x, 0.0f) + __logf(1.0f + e) - 0.69314718055994531f;
}

// ---------------- scratch ----------------
#define MAXN 100000
#define TBL  16384                 // bins over dist in [0,16]; width 1/1024
#define TBL_ROWS (TBL + 2)
__device__ __align__(16) float g_h  [MAXN * NF];
__device__ __align__(16) float g_agg[MAXN * NF];
__device__ __align__(16) float g_h2 [(size_t)MAXN * DIM];
__device__ __align__(16) float g_h3 [(size_t)MAXN * DIM];
__device__ __align__(16) float g_T  [(size_t)TBL_ROWS * NF];   // W(dist)*C(dist)

// =======================================================================
// Table kernel: T[b][:] = (ssp(gauss(d_b)@w1+b1)@w2+b2)*C(d_b), d_b=b/1024
// 4 threads per bin (16 outputs each), ssp intermediate staged in smem.
// =======================================================================
__global__ void __launch_bounds__(128) k_table(
    const float* __restrict__ w1, const float* __restrict__ b1,
    const float* __restrict__ w2, const float* __restrict__ b2)
{
    __shared__ __align__(16) float s_w1[NG * NF];
    __shared__ __align__(16) float s_w2[NF * NF];
    __shared__ __align__(16) float s_b1[NF];
    __shared__ __align__(16) float s_b2[NF];
    __shared__ float s_mid[32][NF + 1];     // padded: conflict-free

    for (int i = threadIdx.x; i < NG * NF; i += blockDim.x) s_w1[i] = w1[i];
    for (int i = threadIdx.x; i < NF * NF; i += blockDim.x) s_w2[i] = w2[i];
    if (threadIdx.x < NF){
        s_b1[threadIdx.x] = b1[threadIdx.x];
        s_b2[threadIdx.x] = b2[threadIdx.x];
    }
    __syncthreads();

    int q  = threadIdx.x & 3;        // output quarter (16 outputs)
    int bl = threadIdx.x >> 2;       // local bin 0..31
    int bin = blockIdx.x * 32 + bl;
    float dist = (float)bin * (1.0f / 1024.0f);

    const float delta = 10.0f / 49.0f;
    const float coeff = -0.5f / (delta * delta);

    // phase A: MLP1 quarter + ssp -> smem
    float acc[16];
    #pragma unroll
    for (int i = 0; i < 16; i++) acc[i] = s_b1[q*16 + i];
    for (int g = 0; g < NG; g++){
        float t  = dist - (float)g * delta;
        float eg = __expf(coeff * t * t);
        #pragma unroll
        for (int i = 0; i < 16; i++) acc[i] = fmaf(eg, s_w1[g*NF + q*16 + i], acc[i]);
    }
    #pragma unroll
    for (int i = 0; i < 16; i++) s_mid[bl][q*16 + i] = sspf(acc[i]);
    __syncthreads();

    // phase B: MLP2 quarter
    float acc2[16];
    #pragma unroll
    for (int i = 0; i < 16; i++) acc2[i] = s_b2[q*16 + i];
    for (int j = 0; j < NF; j++){
        float a = s_mid[bl][j];
        #pragma unroll
        for (int i = 0; i < 16; i++) acc2[i] = fmaf(a, s_w2[j*NF + q*16 + i], acc2[i]);
    }

    if (bin <= TBL){
        float C = 0.5f * (__cosf(dist * 0.31415926535897932f) + 1.0f);
        float* dst = g_T + (size_t)bin * NF + q*16;
        #pragma unroll
        for (int i = 0; i < 16; i++) dst[i] = acc2[i] * C;
    }
}

// =======================================================================
// Edge kernel, coalesced: 16 lanes per edge, lane j owns float4 chunk j.
// =======================================================================
__global__ void __launch_bounds__(256) k_edge(
    const int* __restrict__ ei, const float* __restrict__ pos, int E)
{
    int gid = blockIdx.x * 256 + threadIdx.x;
    int e = gid >> 4;
    int j = gid & 15;
    if (e >= E) return;

    int s = __ldg(&ei[e]);
    int d = __ldg(&ei[E + e]);

    float dx = __ldg(&pos[d*3+0]) - __ldg(&pos[s*3+0]);
    float dy = __ldg(&pos[d*3+1]) - __ldg(&pos[s*3+1]);
    float dz = __ldg(&pos[d*3+2]) - __ldg(&pos[s*3+2]);
    float dist = sqrtf(dx*dx + dy*dy + dz*dz);

    float t = fminf(dist * 1024.0f, 16383.99f);
    int   i = (int)t;
    float f = t - (float)i;

    const float4* tp = (const float4*)(g_T + (size_t)i * NF) + j;
    float4 a  = __ldg(tp);
    float4 b  = __ldg(tp + NF/4);
    float4 hv = __ldg((const float4*)(g_h + (size_t)s * NF) + j);

    float m0 = hv.x * fmaf(f, b.x - a.x, a.x);
    float m1 = hv.y * fmaf(f, b.y - a.y, a.y);
    float m2 = hv.z * fmaf(f, b.z - a.z, a.z);
    float m3 = hv.w * fmaf(f, b.w - a.w, a.w);

    asm volatile("red.global.add.v4.f32 [%0], {%1, %2, %3, %4};"
                 :: "l"(g_agg + (size_t)d * NF + 4*j),
                    "f"(m0), "f"(m1), "f"(m2), "f"(m3)
                 : "memory");
}

// =======================================================================
// Register-tiled GEMM v3b: NC = NO/32 outputs/thread, 3 blocks/SM,
// float4 input loads (4 k's per LDG). Inner loop written with scalar
// array extraction (proven ptxas-friendly form).
// Block = 256 threads: tx 0..31 = output chunk, ty 0..7 = 8-node group.
//   ACT: 0=none, 1=ssp, 2=relu ; RESID adds resid[] after relu
//   ZERO: also zero g_agg rows (node_in)
//   INSEL: 0=ext, 1=g_agg, 2=g_h2, 3=g_h3 ; OUTSEL: 0=ext, 1=g_h, 2=g_h2, 3=g_h3
// =======================================================================
template<int K, int NO, int ACT, bool RESID, bool ZERO, int INSEL, int OUTSEL>
__global__ void __launch_bounds__(256, 3) k_gemm(
    const float* __restrict__ ein, const float* __restrict__ w,
    const float* __restrict__ bias, const float* __restrict__ resid,
    float* __restrict__ eout, int N)
{
    constexpr int NC = NO / 32;          // outputs per thread: 4 (NO=128) or 2 (NO=64)
    constexpr int KS = (K > 64) ? 64 : K;
    constexpr int NSTAGE = K / KS;

    __shared__ __align__(16) float sw[KS * NO];   // <= 32 KB
    __shared__ __align__(16) float sb[NO];

    int tid = threadIdx.x;
    int tx = tid & 31, ty = tid >> 5;
    if (tid < NO) sb[tid] = bias ? bias[tid] : 0.0f;

    const float* inp = (INSEL == 0) ? ein
                     : (INSEL == 1) ? (const float*)g_agg
                     : (INSEL == 2) ? (const float*)g_h2
                     :                (const float*)g_h3;
    float* outp = (OUTSEL == 0) ? eout
                : (OUTSEL == 1) ? (float*)g_h
                : (OUTSEL == 2) ? (float*)g_h2
                :                 (float*)g_h3;

    int base = blockIdx.x * 64 + ty * 8;     // first of this thread's 8 nodes

    // per-node input row pointers (clamped for tail safety; stores are guarded)
    const float4* pr[8];
    #pragma unroll
    for (int r = 0; r < 8; r++){
        int n = base + r; if (n > N - 1) n = N - 1;
        pr[r] = (const float4*)(inp + (size_t)n * K);
    }

    ull acc[8][NC/2];
    #pragma unroll
    for (int r = 0; r < 8; r++)
        #pragma unroll
        for (int j = 0; j < NC/2; j++) acc[r][j] = 0ULL;

    #pragma unroll 1
    for (int st = 0; st < NSTAGE; st++){
        __syncthreads();
        {
            const float4* wsrc = (const float4*)(w + st * KS * NO);
            float4* wdst = (float4*)sw;
            for (int i = tid; i < KS * NO / 4; i += 256) wdst[i] = __ldg(&wsrc[i]);
        }
        __syncthreads();

        const float* swp = sw + tx * NC;

        #pragma unroll 1
        for (int kq = 0; kq < KS/4; kq++){
            // 4 k's worth of inputs per node, scalar-extracted
            float xs[8][4];
            #pragma unroll
            for (int r = 0; r < 8; r++){
                float4 v = __ldg(pr[r] + st*(KS/4) + kq);
                xs[r][0] = v.x; xs[r][1] = v.y; xs[r][2] = v.z; xs[r][3] = v.w;
            }

            #pragma unroll
            for (int q = 0; q < 4; q++){
                int k = kq*4 + q;
                if (NC == 4){
                    ulonglong2 wv = *(const ulonglong2*)(swp + k*NO);
                    #pragma unroll
                    for (int r = 0; r < 8; r++){
                        ull bx = pk2(xs[r][q], xs[r][q]);
                        acc[r][0] = ffma2(bx, wv.x, acc[r][0]);
                        acc[r][1] = ffma2(bx, wv.y, acc[r][1]);
                    }
                } else {
                    ull wv = *(const ull*)(swp + k*NO);
                    #pragma unroll
                    for (int r = 0; r < 8; r++){
                        ull bx = pk2(xs[r][q], xs[r][q]);
                        acc[r][0] = ffma2(bx, wv, acc[r][0]);
                    }
                }
            }
        }
    }

    // epilogue
    const ull* sb2 = (const ull*)(sb + tx*NC);
    #pragma unroll
    for (int r = 0; r < 8; r++){
        int n = base + r;
        if (n >= N) continue;

        if (NC == 4){
            float2 p0 = up2(fadd2(acc[r][0], sb2[0]));
            float2 p1 = up2(fadd2(acc[r][1], sb2[1]));
            float o0 = p0.x, o1 = p0.y, o2 = p1.x, o3 = p1.y;
            if (ACT == 1){ o0 = sspf(o0); o1 = sspf(o1); o2 = sspf(o2); o3 = sspf(o3); }
            if (ACT == 2){
                o0 = fmaxf(o0, 0.f); o1 = fmaxf(o1, 0.f);
                o2 = fmaxf(o2, 0.f); o3 = fmaxf(o3, 0.f);
            }
            if (RESID){
                float4 v = __ldg((const float4*)(resid + (size_t)n*NO + tx*4));
                o0 += v.x; o1 += v.y; o2 += v.z; o3 += v.w;
            }
            *(float4*)(outp + (size_t)n*NO + tx*4) = make_float4(o0, o1, o2, o3);
        } else {
            float2 p = up2(fadd2(acc[r][0], sb2[0]));
            float o0 = p.x, o1 = p.y;
            if (ACT == 1){ o0 = sspf(o0); o1 = sspf(o1); }
            if (ACT == 2){ o0 = fmaxf(o0, 0.f); o1 = fmaxf(o1, 0.f); }
            *(float2*)(outp + (size_t)n*NO + tx*2) = make_float2(o0, o1);
        }

        if (ZERO){   // node_in (NO==64): zero agg[n][tx*2 .. +2)
            *(float2*)(g_agg + (size_t)n*NF + tx*2) = make_float2(0.f, 0.f);
        }
    }
}

// =======================================================================
extern "C" void kernel_launch(void* const* d_in, const int* in_sizes, int n_in,
                              void* d_out, int out_size)
{
    const float* x    = (const float*)d_in[0];
    const float* pos  = (const float*)d_in[1];
    const int*   ei   = (const int*)d_in[2];
    const float* w1   = (const float*)d_in[3];
    const float* b1   = (const float*)d_in[4];
    const float* w2   = (const float*)d_in[5];
    const float* b2   = (const float*)d_in[6];
    const float* cl1  = (const float*)d_in[7];
    const float* cl2  = (const float*)d_in[8];
    const float* cl2b = (const float*)d_in[9];
    const float* ilw  = (const float*)d_in[10];
    const float* ilb  = (const float*)d_in[11];
    const float* l1w  = (const float*)d_in[12];
    const float* l1b  = (const float*)d_in[13];
    float* out = (float*)d_out;

    int N = in_sizes[0] / DIM;
    int E = in_sizes[2] / 2;

    int nb = (N + 63) / 64;
    int tb = (TBL + 1 + 31) / 32;
    long long items = (long long)E * 16;
    int eb = (int)((items + 255) / 256);

    // filter table (independent of node path)
    k_table<<<tb, 128>>>(w1, b1, w2, b2);

    // h = x @ conv_lin1_w ; zero agg
    k_gemm<DIM, NF, 0, false, true, 0, 1><<<nb, 256>>>(x, cl1, nullptr, nullptr, nullptr, N);

    // edge scatter (coalesced, 16 lanes/edge)
    k_edge<<<eb, 256>>>(ei, pos, E);

    // h2 = ssp(agg @ conv_lin2_w + b)
    k_gemm<NF, DIM, 1, false, false, 1, 2><<<nb, 256>>>(nullptr, cl2, cl2b, nullptr, nullptr, N);

    // h3 = h2 @ int_lin_w + b
    k_gemm<DIM, DIM, 0, false, false, 2, 3><<<nb, 256>>>(nullptr, ilw, ilb, nullptr, nullptr, N);

    // out = x + relu(h3 @ lin1_w + b)
    k_gemm<DIM, DIM, 2, true, false, 3, 0><<<nb, 256>>>(nullptr, l1w, l1b, x, out, N);
}

// round 13
// speedup vs baseline: 1.4952x; 1.4952x over previous
#include <cuda_runtime.h>
#include <cstdint>
#include <cstddef>

#define NG   50
#define NF   64
#define DIM  128

typedef unsigned long long ull;

// shifted softplus
__device__ __forceinline__ float sspf(float x){
    float e = __expf(-fabsf(x));
    return fmaxf(x, 0.0f) + __logf(1.0f + e) - 0.69314718055994531f;
}

__device__ __forceinline__ uint32_t f2tf32(float v){
    uint32_t u;
    asm("cvt.rna.tf32.f32 %0, %1;" : "=r"(u) : "f"(v));
    return u;
}

// ---------------- scratch ----------------
#define MAXN 100000
#define TBL  16384                 // bins over dist in [0,16]; width 1/1024
#define TBL_ROWS (TBL + 2)
__device__ __align__(16) float g_h  [MAXN * NF];
__device__ __align__(16) float g_agg[MAXN * NF];
__device__ __align__(16) float g_h2 [(size_t)MAXN * DIM];
__device__ __align__(16) float g_h3 [(size_t)MAXN * DIM];
__device__ __align__(16) float g_T  [(size_t)TBL_ROWS * NF];   // W(dist)*C(dist)

// =======================================================================
// Table kernel: T[b][:] = (ssp(gauss(d_b)@w1+b1)@w2+b2)*C(d_b), d_b=b/1024
// =======================================================================
__global__ void __launch_bounds__(128) k_table(
    const float* __restrict__ w1, const float* __restrict__ b1,
    const float* __restrict__ w2, const float* __restrict__ b2)
{
    __shared__ __align__(16) float s_w1[NG * NF];
    __shared__ __align__(16) float s_w2[NF * NF];
    __shared__ __align__(16) float s_b1[NF];
    __shared__ __align__(16) float s_b2[NF];
    __shared__ float s_mid[32][NF + 1];

    for (int i = threadIdx.x; i < NG * NF; i += blockDim.x) s_w1[i] = w1[i];
    for (int i = threadIdx.x; i < NF * NF; i += blockDim.x) s_w2[i] = w2[i];
    if (threadIdx.x < NF){
        s_b1[threadIdx.x] = b1[threadIdx.x];
        s_b2[threadIdx.x] = b2[threadIdx.x];
    }
    __syncthreads();

    int q  = threadIdx.x & 3;
    int bl = threadIdx.x >> 2;
    int bin = blockIdx.x * 32 + bl;
    float dist = (float)bin * (1.0f / 1024.0f);

    const float delta = 10.0f / 49.0f;
    const float coeff = -0.5f / (delta * delta);

    float acc[16];
    #pragma unroll
    for (int i = 0; i < 16; i++) acc[i] = s_b1[q*16 + i];
    for (int g = 0; g < NG; g++){
        float t  = dist - (float)g * delta;
        float eg = __expf(coeff * t * t);
        #pragma unroll
        for (int i = 0; i < 16; i++) acc[i] = fmaf(eg, s_w1[g*NF + q*16 + i], acc[i]);
    }
    #pragma unroll
    for (int i = 0; i < 16; i++) s_mid[bl][q*16 + i] = sspf(acc[i]);
    __syncthreads();

    float acc2[16];
    #pragma unroll
    for (int i = 0; i < 16; i++) acc2[i] = s_b2[q*16 + i];
    for (int j = 0; j < NF; j++){
        float a = s_mid[bl][j];
        #pragma unroll
        for (int i = 0; i < 16; i++) acc2[i] = fmaf(a, s_w2[j*NF + q*16 + i], acc2[i]);
    }

    if (bin <= TBL){
        float C = 0.5f * (__cosf(dist * 0.31415926535897932f) + 1.0f);
        float* dst = g_T + (size_t)bin * NF + q*16;
        #pragma unroll
        for (int i = 0; i < 16; i++) dst[i] = acc2[i] * C;
    }
}

// =======================================================================
// Edge kernel, coalesced: 16 lanes per edge, lane j owns float4 chunk j.
// =======================================================================
__global__ void __launch_bounds__(256) k_edge(
    const int* __restrict__ ei, const float* __restrict__ pos, int E)
{
    int gid = blockIdx.x * 256 + threadIdx.x;
    int e = gid >> 4;
    int j = gid & 15;
    if (e >= E) return;

    int s = __ldg(&ei[e]);
    int d = __ldg(&ei[E + e]);

    float dx = __ldg(&pos[d*3+0]) - __ldg(&pos[s*3+0]);
    float dy = __ldg(&pos[d*3+1]) - __ldg(&pos[s*3+1]);
    float dz = __ldg(&pos[d*3+2]) - __ldg(&pos[s*3+2]);
    float dist = sqrtf(dx*dx + dy*dy + dz*dz);

    float t = fminf(dist * 1024.0f, 16383.99f);
    int   i = (int)t;
    float f = t - (float)i;

    const float4* tp = (const float4*)(g_T + (size_t)i * NF) + j;
    float4 a  = __ldg(tp);
    float4 b  = __ldg(tp + NF/4);
    float4 hv = __ldg((const float4*)(g_h + (size_t)s * NF) + j);

    float m0 = hv.x * fmaf(f, b.x - a.x, a.x);
    float m1 = hv.y * fmaf(f, b.y - a.y, a.y);
    float m2 = hv.z * fmaf(f, b.z - a.z, a.z);
    float m3 = hv.w * fmaf(f, b.w - a.w, a.w);

    asm volatile("red.global.add.v4.f32 [%0], {%1, %2, %3, %4};"
                 :: "l"(g_agg + (size_t)d * NF + 4*j),
                    "f"(m0), "f"(m1), "f"(m2), "f"(m3)
                 : "memory");
}

// =======================================================================
// Tensor-core GEMM via portable mma.sync (tf32, m16n8k8):
//   OUT[n,:NO] = act(IN[n,:K] @ W[K,NO] + bias)
// CTA: 256 thr = 8 warps, tile M=128 nodes x NO cols.
// Warp tile: 32 rows x NO/2 cols (2 M-tiles x NT N-tiles of 16x8).
// K staged in 32-wide chunks; A smem [m][k], B smem [n][k], both row
// stride 36 floats -> fragment gathers bank-conflict-free ((4g+t)%32).
// fp32 -> tf32 via cvt.rna at staging.
//   ACT: 0=none, 1=ssp, 2=relu ; RESID adds resid[] ; ZERO zeroes g_agg
//   INSEL: 0=ext, 1=g_agg, 2=g_h2, 3=g_h3 ; OUTSEL: 0=ext, 1=g_h, 2=g_h2, 3=g_h3
// =======================================================================
template<int K, int NO, int ACT, bool RESID, bool ZERO, int INSEL, int OUTSEL>
__global__ void __launch_bounds__(256, 2) k_mma(
    const float* __restrict__ ein, const float* __restrict__ w,
    const float* __restrict__ bias, const float* __restrict__ resid,
    float* __restrict__ eout, int N)
{
    constexpr int KS  = 32;
    constexpr int NCH = K / KS;
    constexpr int SA  = 36;              // padded row stride (floats)
    constexpr int WCOLS = NO / 2;        // cols per warp
    constexpr int NT = WCOLS / 8;        // 8 (NO=128) or 4 (NO=64)

    __shared__ __align__(16) float As[128 * SA];   // 18 KB
    __shared__ __align__(16) float Bs[NO  * SA];   // 18 / 9 KB
    __shared__ float sb[NO];

    int tid  = threadIdx.x;
    int wid  = tid >> 5, lane = tid & 31;
    int g    = lane >> 2, t = lane & 3;
    int wm   = wid & 3;          // 4 row-blocks of 32
    int wn   = wid >> 2;         // 2 col-blocks of WCOLS

    const float* inp = (INSEL == 0) ? ein
                     : (INSEL == 1) ? (const float*)g_agg
                     : (INSEL == 2) ? (const float*)g_h2
                     :                (const float*)g_h3;
    float* outp = (OUTSEL == 0) ? eout
                : (OUTSEL == 1) ? (float*)g_h
                : (OUTSEL == 2) ? (float*)g_h2
                :                 (float*)g_h3;

    if (tid < NO) sb[tid] = bias ? bias[tid] : 0.0f;

    int blockM = blockIdx.x * 128;

    float acc[2][NT][4];
    #pragma unroll
    for (int mt = 0; mt < 2; mt++)
        #pragma unroll
        for (int nt = 0; nt < NT; nt++)
            #pragma unroll
            for (int c = 0; c < 4; c++) acc[mt][nt][c] = 0.0f;

    #pragma unroll 1
    for (int c = 0; c < NCH; c++){
        int k0 = c * KS;
        __syncthreads();   // protect As/Bs from previous chunk's readers

        // stage A: 128 rows x 32 k, tf32-converted, float4 stores
        for (int i = tid; i < 128*8; i += 256){
            int row = i >> 3, kq = i & 7;
            int node = blockM + row; if (node > N-1) node = N-1;
            float4 v = __ldg((const float4*)(inp + (size_t)node*K + k0) + kq);
            float4 o;
            o.x = __uint_as_float(f2tf32(v.x));
            o.y = __uint_as_float(f2tf32(v.y));
            o.z = __uint_as_float(f2tf32(v.z));
            o.w = __uint_as_float(f2tf32(v.w));
            *(float4*)(As + row*SA + kq*4) = o;
        }
        // stage B transposed: Bs[n][kl] = w[(k0+kl)*NO + n]
        for (int i = tid; i < NO*32; i += 256){
            int kl = i / NO, n = i - kl*NO;
            float v = __ldg(w + (size_t)(k0+kl)*NO + n);
            Bs[n*SA + kl] = __uint_as_float(f2tf32(v));
        }
        __syncthreads();

        #pragma unroll
        for (int kt = 0; kt < 4; kt++){
            int kk = kt * 8;
            uint32_t af[2][4];
            #pragma unroll
            for (int mt = 0; mt < 2; mt++){
                int m0 = wm*32 + mt*16;
                af[mt][0] = __float_as_uint(As[(m0 + g    )*SA + kk + t    ]);
                af[mt][1] = __float_as_uint(As[(m0 + 8 + g)*SA + kk + t    ]);
                af[mt][2] = __float_as_uint(As[(m0 + g    )*SA + kk + t + 4]);
                af[mt][3] = __float_as_uint(As[(m0 + 8 + g)*SA + kk + t + 4]);
            }
            uint32_t bf[NT][2];
            #pragma unroll
            for (int nt = 0; nt < NT; nt++){
                int n0 = wn*WCOLS + nt*8;
                bf[nt][0] = __float_as_uint(Bs[(n0 + g)*SA + kk + t    ]);
                bf[nt][1] = __float_as_uint(Bs[(n0 + g)*SA + kk + t + 4]);
            }
            #pragma unroll
            for (int mt = 0; mt < 2; mt++)
                #pragma unroll
                for (int nt = 0; nt < NT; nt++){
                    asm volatile(
                        "mma.sync.aligned.m16n8k8.row.col.f32.tf32.tf32.f32 "
                        "{%0,%1,%2,%3}, {%4,%5,%6,%7}, {%8,%9}, {%0,%1,%2,%3};"
                        : "+f"(acc[mt][nt][0]), "+f"(acc[mt][nt][1]),
                          "+f"(acc[mt][nt][2]), "+f"(acc[mt][nt][3])
                        : "r"(af[mt][0]), "r"(af[mt][1]),
                          "r"(af[mt][2]), "r"(af[mt][3]),
                          "r"(bf[nt][0]), "r"(bf[nt][1]));
                }
        }
    }

    // epilogue: c0/c1 at (row, col..col+1), c2/c3 at (row+8, col..col+1)
    #pragma unroll
    for (int mt = 0; mt < 2; mt++){
        #pragma unroll
        for (int nt = 0; nt < NT; nt++){
            int col = wn*WCOLS + nt*8 + 2*t;
            float b0 = sb[col], b1 = sb[col+1];
            #pragma unroll
            for (int half = 0; half < 2; half++){
                int node = blockM + wm*32 + mt*16 + g + half*8;
                if (node >= N) continue;
                float v0 = acc[mt][nt][2*half]     + b0;
                float v1 = acc[mt][nt][2*half + 1] + b1;
                if (ACT == 1){ v0 = sspf(v0); v1 = sspf(v1); }
                if (ACT == 2){ v0 = fmaxf(v0, 0.f); v1 = fmaxf(v1, 0.f); }
                if (RESID){
                    float2 rv = *(const float2*)(resid + (size_t)node*NO + col);
                    v0 += rv.x; v1 += rv.y;
                }
                *(float2*)(outp + (size_t)node*NO + col) = make_float2(v0, v1);
            }
        }
    }

    if (ZERO){
        for (int i = tid; i < 128*NF; i += 256){
            int row = i >> 6;
            int node = blockM + row;
            if (node < N) g_agg[(size_t)node*NF + (i & 63)] = 0.0f;
        }
    }
}

// =======================================================================
extern "C" void kernel_launch(void* const* d_in, const int* in_sizes, int n_in,
                              void* d_out, int out_size)
{
    const float* x    = (const float*)d_in[0];
    const float* pos  = (const float*)d_in[1];
    const int*   ei   = (const int*)d_in[2];
    const float* w1   = (const float*)d_in[3];
    const float* b1   = (const float*)d_in[4];
    const float* w2   = (const float*)d_in[5];
    const float* b2   = (const float*)d_in[6];
    const float* cl1  = (const float*)d_in[7];
    const float* cl2  = (const float*)d_in[8];
    const float* cl2b = (const float*)d_in[9];
    const float* ilw  = (const float*)d_in[10];
    const float* ilb  = (const float*)d_in[11];
    const float* l1w  = (const float*)d_in[12];
    const float* l1b  = (const float*)d_in[13];
    float* out = (float*)d_out;

    int N = in_sizes[0] / DIM;
    int E = in_sizes[2] / 2;

    int nb = (N + 127) / 128;
    int tb = (TBL + 1 + 31) / 32;
    long long items = (long long)E * 16;
    int eb = (int)((items + 255) / 256);

    // filter table (independent of node path)
    k_table<<<tb, 128>>>(w1, b1, w2, b2);

    // h = x @ conv_lin1_w ; zero agg
    k_mma<DIM, NF, 0, false, true, 0, 1><<<nb, 256>>>(x, cl1, nullptr, nullptr, nullptr, N);

    // edge scatter (coalesced, 16 lanes/edge)
    k_edge<<<eb, 256>>>(ei, pos, E);

    // h2 = ssp(agg @ conv_lin2_w + b)
    k_mma<NF, DIM, 1, false, false, 1, 2><<<nb, 256>>>(nullptr, cl2, cl2b, nullptr, nullptr, N);

    // h3 = h2 @ int_lin_w + b
    k_mma<DIM, DIM, 0, false, false, 2, 3><<<nb, 256>>>(nullptr, ilw, ilb, nullptr, nullptr, N);

    // out = x + relu(h3 @ lin1_w + b)
    k_mma<DIM, DIM, 2, true, false, 3, 0><<<nb, 256>>>(nullptr, l1w, l1b, x, out, N);
}

// round 14
// speedup vs baseline: 1.9307x; 1.2913x over previous
#include <cuda_runtime.h>
#include <cstdint>
#include <cstddef>

#define NG   50
#define NF   64
#define DIM  128

typedef unsigned long long ull;

// shifted softplus
__device__ __forceinline__ float sspf(float x){
    float e = __expf(-fabsf(x));
    return fmaxf(x, 0.0f) + __logf(1.0f + e) - 0.69314718055994531f;
}

__device__ __forceinline__ uint32_t smem_u32(const void* p){
    uint32_t a;
    asm("{ .reg .u64 t; cvta.to.shared.u64 t, %1; cvt.u32.u64 %0, t; }"
        : "=r"(a) : "l"(p));
    return a;
}
__device__ __forceinline__ void cp16(uint32_t dst, const void* src){
    asm volatile("cp.async.cg.shared.global [%0], [%1], 16;"
                 :: "r"(dst), "l"(src) : "memory");
}

// ---------------- scratch ----------------
#define MAXN 100000
#define TBL  16384                 // bins over dist in [0,16]; width 1/1024
#define TBL_ROWS (TBL + 2)
__device__ __align__(16) float g_h  [MAXN * NF];
__device__ __align__(16) float g_agg[MAXN * NF];
__device__ __align__(16) float g_h2 [(size_t)MAXN * DIM];
__device__ __align__(16) float g_h3 [(size_t)MAXN * DIM];
__device__ __align__(16) float g_T  [(size_t)TBL_ROWS * NF];   // W(dist)*C(dist)

// =======================================================================
// Table kernel: T[b][:] = (ssp(gauss(d_b)@w1+b1)@w2+b2)*C(d_b), d_b=b/1024
// =======================================================================
__global__ void __launch_bounds__(128) k_table(
    const float* __restrict__ w1, const float* __restrict__ b1,
    const float* __restrict__ w2, const float* __restrict__ b2)
{
    __shared__ __align__(16) float s_w1[NG * NF];
    __shared__ __align__(16) float s_w2[NF * NF];
    __shared__ __align__(16) float s_b1[NF];
    __shared__ __align__(16) float s_b2[NF];
    __shared__ float s_mid[32][NF + 1];

    for (int i = threadIdx.x; i < NG * NF; i += blockDim.x) s_w1[i] = w1[i];
    for (int i = threadIdx.x; i < NF * NF; i += blockDim.x) s_w2[i] = w2[i];
    if (threadIdx.x < NF){
        s_b1[threadIdx.x] = b1[threadIdx.x];
        s_b2[threadIdx.x] = b2[threadIdx.x];
    }
    __syncthreads();

    int q  = threadIdx.x & 3;
    int bl = threadIdx.x >> 2;
    int bin = blockIdx.x * 32 + bl;
    float dist = (float)bin * (1.0f / 1024.0f);

    const float delta = 10.0f / 49.0f;
    const float coeff = -0.5f / (delta * delta);

    float acc[16];
    #pragma unroll
    for (int i = 0; i < 16; i++) acc[i] = s_b1[q*16 + i];
    for (int g = 0; g < NG; g++){
        float t  = dist - (float)g * delta;
        float eg = __expf(coeff * t * t);
        #pragma unroll
        for (int i = 0; i < 16; i++) acc[i] = fmaf(eg, s_w1[g*NF + q*16 + i], acc[i]);
    }
    #pragma unroll
    for (int i = 0; i < 16; i++) s_mid[bl][q*16 + i] = sspf(acc[i]);
    __syncthreads();

    float acc2[16];
    #pragma unroll
    for (int i = 0; i < 16; i++) acc2[i] = s_b2[q*16 + i];
    for (int j = 0; j < NF; j++){
        float a = s_mid[bl][j];
        #pragma unroll
        for (int i = 0; i < 16; i++) acc2[i] = fmaf(a, s_w2[j*NF + q*16 + i], acc2[i]);
    }

    if (bin <= TBL){
        float C = 0.5f * (__cosf(dist * 0.31415926535897932f) + 1.0f);
        float* dst = g_T + (size_t)bin * NF + q*16;
        #pragma unroll
        for (int i = 0; i < 16; i++) dst[i] = acc2[i] * C;
    }
}

// =======================================================================
// Edge kernel, coalesced: 16 lanes per edge, lane j owns float4 chunk j.
// =======================================================================
__global__ void __launch_bounds__(256) k_edge(
    const int* __restrict__ ei, const float* __restrict__ pos, int E)
{
    int gid = blockIdx.x * 256 + threadIdx.x;
    int e = gid >> 4;
    int j = gid & 15;
    if (e >= E) return;

    int s = __ldg(&ei[e]);
    int d = __ldg(&ei[E + e]);

    float dx = __ldg(&pos[d*3+0]) - __ldg(&pos[s*3+0]);
    float dy = __ldg(&pos[d*3+1]) - __ldg(&pos[s*3+1]);
    float dz = __ldg(&pos[d*3+2]) - __ldg(&pos[s*3+2]);
    float dist = sqrtf(dx*dx + dy*dy + dz*dz);

    float t = fminf(dist * 1024.0f, 16383.99f);
    int   i = (int)t;
    float f = t - (float)i;

    const float4* tp = (const float4*)(g_T + (size_t)i * NF) + j;
    float4 a  = __ldg(tp);
    float4 b  = __ldg(tp + NF/4);
    float4 hv = __ldg((const float4*)(g_h + (size_t)s * NF) + j);

    float m0 = hv.x * fmaf(f, b.x - a.x, a.x);
    float m1 = hv.y * fmaf(f, b.y - a.y, a.y);
    float m2 = hv.z * fmaf(f, b.z - a.z, a.z);
    float m3 = hv.w * fmaf(f, b.w - a.w, a.w);

    asm volatile("red.global.add.v4.f32 [%0], {%1, %2, %3, %4};"
                 :: "l"(g_agg + (size_t)d * NF + 4*j),
                    "f"(m0), "f"(m1), "f"(m2), "f"(m3)
                 : "memory");
}

// =======================================================================
// Tensor-core GEMM (mma.sync tf32) with cp.async double-buffered pipeline.
//   OUT[n,:NO] = act(IN[n,:K] @ W[K,NO] + bias)
// CTA: 256 thr = 8 warps, tile M=128 x NO. K in 32-wide chunks.
// Smem (dynamic): A[2][128][SA=36] ([m][k]); B[2][32][SB] ([k][n], raw
// rows of w -> cp.async friendly). SB=136/72 (==8 mod 32: conflict-free
// b-fragment gathers (SB*t+g)%32 distinct; SA==4 mod 32 for a-fragments).
// fp32 fed raw to tf32 MMA (HW truncation).
//   ACT: 0=none, 1=ssp, 2=relu ; RESID adds resid[] ; ZERO zeroes g_agg
//   INSEL: 0=ext, 1=g_agg, 2=g_h2, 3=g_h3 ; OUTSEL: 0=ext, 1=g_h, 2=g_h2, 3=g_h3
// =======================================================================
template<int K, int NO, int ACT, bool RESID, bool ZERO, int INSEL, int OUTSEL>
__global__ void __launch_bounds__(256, 2) k_mma(
    const float* __restrict__ ein, const float* __restrict__ w,
    const float* __restrict__ bias, const float* __restrict__ resid,
    float* __restrict__ eout, int N)
{
    constexpr int KS  = 32;
    constexpr int NCH = K / KS;
    constexpr int SA  = 36;                       // 36 % 32 == 4
    constexpr int SB  = (NO == 128) ? 136 : 72;   // % 32 == 8
    constexpr int ASZ = 128 * SA;                 // floats per A buffer
    constexpr int BSZ = 32 * SB;                  // floats per B buffer
    constexpr int WCOLS = NO / 2;
    constexpr int NT = WCOLS / 8;

    extern __shared__ __align__(16) float dsm[];  // [A0|A1|B0|B1]
    __shared__ float sb[NO];

    int tid  = threadIdx.x;
    int wid  = tid >> 5, lane = tid & 31;
    int g    = lane >> 2, t = lane & 3;
    int wm   = wid & 3;
    int wn   = wid >> 2;

    const float* inp = (INSEL == 0) ? ein
                     : (INSEL == 1) ? (const float*)g_agg
                     : (INSEL == 2) ? (const float*)g_h2
                     :                (const float*)g_h3;
    float* outp = (OUTSEL == 0) ? eout
                : (OUTSEL == 1) ? (float*)g_h
                : (OUTSEL == 2) ? (float*)g_h2
                :                 (float*)g_h3;

    if (tid < NO) sb[tid] = bias ? bias[tid] : 0.0f;

    int blockM = blockIdx.x * 128;
    uint32_t sbase = smem_u32(dsm);

    float acc[2][NT][4];
    #pragma unroll
    for (int mt = 0; mt < 2; mt++)
        #pragma unroll
        for (int nt = 0; nt < NT; nt++)
            #pragma unroll
            for (int c = 0; c < 4; c++) acc[mt][nt][c] = 0.0f;

    // ---- async stage issue (A: 128x32, B: 32xNO) ----
    auto issue = [&](int c, int buf){
        int k0 = c * KS;
        for (int i = tid; i < 128*8; i += 256){
            int row = i >> 3, kq = i & 7;
            int node = blockM + row; if (node > N-1) node = N-1;
            cp16(sbase + (buf*ASZ + row*SA + kq*4)*4,
                 inp + (size_t)node*K + k0 + kq*4);
        }
        for (int i = tid; i < 32*(NO/4); i += 256){
            int kl = i / (NO/4), nq = i % (NO/4);
            cp16(sbase + (2*ASZ + buf*BSZ + kl*SB + nq*4)*4,
                 w + (size_t)(k0+kl)*NO + nq*4);
        }
        asm volatile("cp.async.commit_group;" ::: "memory");
    };

    issue(0, 0);

    #pragma unroll 1
    for (int c = 0; c < NCH; c++){
        if (c + 1 < NCH) issue(c+1, (c+1) & 1);
        if (c + 1 < NCH) asm volatile("cp.async.wait_group 1;" ::: "memory");
        else             asm volatile("cp.async.wait_group 0;" ::: "memory");
        __syncthreads();

        const float* As = dsm + (c & 1) * ASZ;
        const float* Bs = dsm + 2*ASZ + (c & 1) * BSZ;

        #pragma unroll
        for (int kt = 0; kt < 4; kt++){
            int kk = kt * 8;
            uint32_t af[2][4];
            #pragma unroll
            for (int mt = 0; mt < 2; mt++){
                int m0 = wm*32 + mt*16;
                af[mt][0] = __float_as_uint(As[(m0 + g    )*SA + kk + t    ]);
                af[mt][1] = __float_as_uint(As[(m0 + 8 + g)*SA + kk + t    ]);
                af[mt][2] = __float_as_uint(As[(m0 + g    )*SA + kk + t + 4]);
                af[mt][3] = __float_as_uint(As[(m0 + 8 + g)*SA + kk + t + 4]);
            }
            uint32_t bf[NT][2];
            #pragma unroll
            for (int nt = 0; nt < NT; nt++){
                int n0 = wn*WCOLS + nt*8;
                bf[nt][0] = __float_as_uint(Bs[(kk + t    )*SB + n0 + g]);
                bf[nt][1] = __float_as_uint(Bs[(kk + t + 4)*SB + n0 + g]);
            }
            #pragma unroll
            for (int mt = 0; mt < 2; mt++)
                #pragma unroll
                for (int nt = 0; nt < NT; nt++){
                    asm volatile(
                        "mma.sync.aligned.m16n8k8.row.col.f32.tf32.tf32.f32 "
                        "{%0,%1,%2,%3}, {%4,%5,%6,%7}, {%8,%9}, {%0,%1,%2,%3};"
                        : "+f"(acc[mt][nt][0]), "+f"(acc[mt][nt][1]),
                          "+f"(acc[mt][nt][2]), "+f"(acc[mt][nt][3])
                        : "r"(af[mt][0]), "r"(af[mt][1]),
                          "r"(af[mt][2]), "r"(af[mt][3]),
                          "r"(bf[nt][0]), "r"(bf[nt][1]));
                }
        }
        __syncthreads();   // buffer reuse fence (buf c&1 re-filled at c+2)
    }

    // epilogue: c0/c1 at (row, col..col+1), c2/c3 at (row+8, col..col+1)
    #pragma unroll
    for (int mt = 0; mt < 2; mt++){
        #pragma unroll
        for (int nt = 0; nt < NT; nt++){
            int col = wn*WCOLS + nt*8 + 2*t;
            float b0 = sb[col], b1 = sb[col+1];
            #pragma unroll
            for (int half = 0; half < 2; half++){
                int node = blockM + wm*32 + mt*16 + g + half*8;
                if (node >= N) continue;
                float v0 = acc[mt][nt][2*half]     + b0;
                float v1 = acc[mt][nt][2*half + 1] + b1;
                if (ACT == 1){ v0 = sspf(v0); v1 = sspf(v1); }
                if (ACT == 2){ v0 = fmaxf(v0, 0.f); v1 = fmaxf(v1, 0.f); }
                if (RESID){
                    float2 rv = *(const float2*)(resid + (size_t)node*NO + col);
                    v0 += rv.x; v1 += rv.y;
                }
                *(float2*)(outp + (size_t)node*NO + col) = make_float2(v0, v1);
            }
        }
    }

    if (ZERO){
        for (int i = tid; i < 128*NF; i += 256){
            int row = i >> 6;
            int node = blockM + row;
            if (node < N) g_agg[(size_t)node*NF + (i & 63)] = 0.0f;
        }
    }
}

// =======================================================================
extern "C" void kernel_launch(void* const* d_in, const int* in_sizes, int n_in,
                              void* d_out, int out_size)
{
    const float* x    = (const float*)d_in[0];
    const float* pos  = (const float*)d_in[1];
    const int*   ei   = (const int*)d_in[2];
    const float* w1   = (const float*)d_in[3];
    const float* b1   = (const float*)d_in[4];
    const float* w2   = (const float*)d_in[5];
    const float* b2   = (const float*)d_in[6];
    const float* cl1  = (const float*)d_in[7];
    const float* cl2  = (const float*)d_in[8];
    const float* cl2b = (const float*)d_in[9];
    const float* ilw  = (const float*)d_in[10];
    const float* ilb  = (const float*)d_in[11];
    const float* l1w  = (const float*)d_in[12];
    const float* l1b  = (const float*)d_in[13];
    float* out = (float*)d_out;

    int N = in_sizes[0] / DIM;
    int E = in_sizes[2] / 2;

    int nb = (N + 127) / 128;
    int tb = (TBL + 1 + 31) / 32;
    long long items = (long long)E * 16;
    int eb = (int)((items + 255) / 256);

    // dynamic smem: A 2*128*36 + B 2*32*SB floats
    constexpr int SM128 = (2*128*36 + 2*32*136) * 4;   // NO=128: 71680 B
    constexpr int SM64  = (2*128*36 + 2*32*72)  * 4;   // NO=64:  55296 B

    cudaFuncSetAttribute(k_mma<DIM, NF, 0, false, true, 0, 1>,
                         cudaFuncAttributeMaxDynamicSharedMemorySize, SM64);
    cudaFuncSetAttribute(k_mma<NF, DIM, 1, false, false, 1, 2>,
                         cudaFuncAttributeMaxDynamicSharedMemorySize, SM128);
    cudaFuncSetAttribute(k_mma<DIM, DIM, 0, false, false, 2, 3>,
                         cudaFuncAttributeMaxDynamicSharedMemorySize, SM128);
    cudaFuncSetAttribute(k_mma<DIM, DIM, 2, true, false, 3, 0>,
                         cudaFuncAttributeMaxDynamicSharedMemorySize, SM128);

    // filter table (independent of node path)
    k_table<<<tb, 128>>>(w1, b1, w2, b2);

    // h = x @ conv_lin1_w ; zero agg
    k_mma<DIM, NF, 0, false, true, 0, 1><<<nb, 256, SM64>>>(x, cl1, nullptr, nullptr, nullptr, N);

    // edge scatter (coalesced, 16 lanes/edge)
    k_edge<<<eb, 256>>>(ei, pos, E);

    // h2 = ssp(agg @ conv_lin2_w + b)
    k_mma<NF, DIM, 1, false, false, 1, 2><<<nb, 256, SM128>>>(nullptr, cl2, cl2b, nullptr, nullptr, N);

    // h3 = h2 @ int_lin_w + b
    k_mma<DIM, DIM, 0, false, false, 2, 3><<<nb, 256, SM128>>>(nullptr, ilw, ilb, nullptr, nullptr, N);

    // out = x + relu(h3 @ lin1_w + b)
    k_mma<DIM, DIM, 2, true, false, 3, 0><<<nb, 256, SM128>>>(nullptr, l1w, l1b, x, out, N);
}